// round 2
// baseline (speedup 1.0000x reference)
#include <cuda_runtime.h>
#include <math.h>

// Problem constants
#define BB 4
#define TT 1024
#define DD 1024
#define HH 16
#define DKK 64
#define DFF 4096
#define MROWS (BB*TT)            // 4096
#define LNEPS 1e-5f

// ---------------------------------------------------------------------------
// Scratch (static __device__ arrays — no allocation allowed)
// ---------------------------------------------------------------------------
__device__ float g_q[MROWS*DD];
__device__ float g_k[MROWS*DD];
__device__ float g_v[MROWS*DD];
__device__ float g_att[MROWS*DD];
__device__ float g_scores[(size_t)BB*HH*TT*TT];   // 256 MB
__device__ float g_x1[MROWS*DD];
__device__ float g_hid[(size_t)MROWS*DFF];        // 64 MB
__device__ float g_ff[MROWS*DD];

// ---------------------------------------------------------------------------
// Generic tiled SGEMM: C[M,N] = A[M,K] @ B[K,N] (+bias, optional ReLU)
// 128x128 tile, BK=8, 256 threads, 8x8 per thread.
// Software-pipelined: next K-tile's global loads are issued before the
// compute loop so LDG latency overlaps FMA work.
// Requires M%128==0, N%128==0, K%8==0 (all shapes here satisfy this).
// ---------------------------------------------------------------------------
__global__ __launch_bounds__(256) void sgemm_kernel(
    const float* __restrict__ A, const float* __restrict__ B,
    float* __restrict__ C, int M, int N, int K,
    const float* __restrict__ bias, int relu)
{
    __shared__ __align__(16) float As[8][128];
    __shared__ __align__(16) float Bs[8][128];

    const int tid = threadIdx.x;
    const int brow = blockIdx.y;       // M tile
    const int bcol = blockIdx.x;       // N tile

    const float* Ab = A + (size_t)brow * 128 * K;
    const float* Bb = B + (size_t)bcol * 128;

    const int a_r = tid >> 1;          // 0..127
    const int a_c = (tid & 1) * 4;     // 0 or 4
    const int b_r = tid >> 5;          // 0..7
    const int b_c = (tid & 31) * 4;    // 0..124

    const int ty = tid >> 4;           // 0..15
    const int tx = tid & 15;           // 0..15

    float acc[8][8];
    #pragma unroll
    for (int i = 0; i < 8; i++)
        #pragma unroll
        for (int j = 0; j < 8; j++) acc[i][j] = 0.f;

    // Prologue: load first K-tile into registers
    float4 av = *(const float4*)(Ab + (size_t)a_r * K + a_c);
    float4 bv = *(const float4*)(Bb + (size_t)b_r * N + b_c);

    for (int kt = 0; kt < K; kt += 8) {
        // Commit current tile to shared
        As[a_c + 0][a_r] = av.x;
        As[a_c + 1][a_r] = av.y;
        As[a_c + 2][a_r] = av.z;
        As[a_c + 3][a_r] = av.w;
        *(float4*)&Bs[b_r][b_c] = bv;
        __syncthreads();

        // Prefetch next tile (overlaps with the FMA loop below)
        if (kt + 8 < K) {
            av = *(const float4*)(Ab + (size_t)a_r * K + kt + 8 + a_c);
            bv = *(const float4*)(Bb + (size_t)(kt + 8 + b_r) * N + b_c);
        }

        #pragma unroll
        for (int k = 0; k < 8; k++) {
            float4 a0 = *(const float4*)&As[k][ty * 8];
            float4 a1 = *(const float4*)&As[k][ty * 8 + 4];
            float4 b0 = *(const float4*)&Bs[k][tx * 8];
            float4 b1 = *(const float4*)&Bs[k][tx * 8 + 4];
            float a[8] = {a0.x,a0.y,a0.z,a0.w,a1.x,a1.y,a1.z,a1.w};
            float b[8] = {b0.x,b0.y,b0.z,b0.w,b1.x,b1.y,b1.z,b1.w};
            #pragma unroll
            for (int i = 0; i < 8; i++)
                #pragma unroll
                for (int j = 0; j < 8; j++)
                    acc[i][j] = fmaf(a[i], b[j], acc[i][j]);
        }
        __syncthreads();
    }

    const int row0 = brow * 128 + ty * 8;
    const int col0 = bcol * 128 + tx * 8;
    float bsv[8];
    #pragma unroll
    for (int j = 0; j < 8; j++)
        bsv[j] = bias ? bias[col0 + j] : 0.f;

    #pragma unroll
    for (int i = 0; i < 8; i++) {
        float out[8];
        #pragma unroll
        for (int j = 0; j < 8; j++) {
            float v = acc[i][j] + bsv[j];
            out[j] = relu ? fmaxf(v, 0.f) : v;
        }
        float* Cp = C + (size_t)(row0 + i) * N + col0;
        *(float4*)(Cp)     = make_float4(out[0], out[1], out[2], out[3]);
        *(float4*)(Cp + 4) = make_float4(out[4], out[5], out[6], out[7]);
    }
}

// ---------------------------------------------------------------------------
// Attention scores: for each (b,h): S[i,j] = (Q_h[i,:] . K_h[j,:]) * 0.125
// Q,K stored interleaved in projection output: row (b*T+t), cols h*64..h*64+63.
// Block computes a 64x64 tile of S. grid = (T/64, T/64, B*H).
// ---------------------------------------------------------------------------
__global__ __launch_bounds__(256) void attn_scores_kernel(
    const float* __restrict__ Q, const float* __restrict__ K,
    float* __restrict__ S)
{
    __shared__ __align__(16) float Qs[64][65];   // [d][i]
    __shared__ __align__(16) float Ks[64][65];   // [d][j]

    const int tid = threadIdx.x;
    const int bh = blockIdx.z;
    const int b  = bh >> 4;            // / HH
    const int h  = bh & 15;            // % HH
    const int i0 = blockIdx.y * 64;
    const int j0 = blockIdx.x * 64;

    const int rr = tid >> 4;           // 0..15
    const int c4 = (tid & 15) * 4;     // 0..60

    #pragma unroll
    for (int it = 0; it < 4; it++) {
        int r = it * 16 + rr;
        float4 qv = *(const float4*)(Q + (size_t)(b*TT + i0 + r) * DD + h*DKK + c4);
        float4 kv = *(const float4*)(K + (size_t)(b*TT + j0 + r) * DD + h*DKK + c4);
        Qs[c4+0][r] = qv.x; Qs[c4+1][r] = qv.y; Qs[c4+2][r] = qv.z; Qs[c4+3][r] = qv.w;
        Ks[c4+0][r] = kv.x; Ks[c4+1][r] = kv.y; Ks[c4+2][r] = kv.z; Ks[c4+3][r] = kv.w;
    }
    __syncthreads();

    const int ty = tid >> 4;           // row quad
    const int tx = tid & 15;           // col quad
    float acc[4][4];
    #pragma unroll
    for (int i = 0; i < 4; i++)
        #pragma unroll
        for (int j = 0; j < 4; j++) acc[i][j] = 0.f;

    #pragma unroll 8
    for (int d = 0; d < 64; d++) {
        float a[4], bb2[4];
        #pragma unroll
        for (int i = 0; i < 4; i++) a[i]   = Qs[d][ty*4 + i];
        #pragma unroll
        for (int j = 0; j < 4; j++) bb2[j] = Ks[d][tx*4 + j];
        #pragma unroll
        for (int i = 0; i < 4; i++)
            #pragma unroll
            for (int j = 0; j < 4; j++)
                acc[i][j] = fmaf(a[i], bb2[j], acc[i][j]);
    }

    #pragma unroll
    for (int i = 0; i < 4; i++) {
        float* Sp = S + ((size_t)bh * TT + i0 + ty*4 + i) * TT + j0 + tx*4;
        *(float4*)Sp = make_float4(acc[i][0]*0.125f, acc[i][1]*0.125f,
                                   acc[i][2]*0.125f, acc[i][3]*0.125f);
    }
}

// ---------------------------------------------------------------------------
// Row softmax over T=1024 columns. One block (256 threads) per row.
// grid = B*H*T
// ---------------------------------------------------------------------------
__global__ __launch_bounds__(256) void softmax_kernel(float* __restrict__ S)
{
    __shared__ float red[256];
    const int tid = threadIdx.x;
    float* p = S + (size_t)blockIdx.x * TT;

    float v[4];
    #pragma unroll
    for (int u = 0; u < 4; u++) v[u] = p[tid + 256*u];

    float m = fmaxf(fmaxf(v[0], v[1]), fmaxf(v[2], v[3]));
    red[tid] = m;
    __syncthreads();
    for (int s = 128; s > 0; s >>= 1) {
        if (tid < s) red[tid] = fmaxf(red[tid], red[tid + s]);
        __syncthreads();
    }
    m = red[0];
    __syncthreads();

    float e[4], sum = 0.f;
    #pragma unroll
    for (int u = 0; u < 4; u++) { e[u] = __expf(v[u] - m); sum += e[u]; }
    red[tid] = sum;
    __syncthreads();
    for (int s = 128; s > 0; s >>= 1) {
        if (tid < s) red[tid] += red[tid + s];
        __syncthreads();
    }
    float inv = 1.f / red[0];

    #pragma unroll
    for (int u = 0; u < 4; u++) p[tid + 256*u] = e[u] * inv;
}

// ---------------------------------------------------------------------------
// Attention output: O[i,d] = sum_j P[i,j] * V_h[j,d], per (b,h).
// Block computes 64 rows x 64 (full DK) of O. grid = (T/64, 1, B*H).
// ---------------------------------------------------------------------------
__global__ __launch_bounds__(256) void attn_out_kernel(
    const float* __restrict__ P, const float* __restrict__ V,
    float* __restrict__ O)
{
    __shared__ __align__(16) float Ps[64][65];   // [j][i]
    __shared__ __align__(16) float Vs[64][64];   // [j][d]

    const int tid = threadIdx.x;
    const int bh = blockIdx.z;
    const int b  = bh >> 4;
    const int h  = bh & 15;
    const int i0 = blockIdx.x * 64;

    const int rr = tid >> 4;
    const int c4 = (tid & 15) * 4;
    const int ty = tid >> 4;
    const int tx = tid & 15;

    float acc[4][4];
    #pragma unroll
    for (int i = 0; i < 4; i++)
        #pragma unroll
        for (int j = 0; j < 4; j++) acc[i][j] = 0.f;

    for (int j0 = 0; j0 < TT; j0 += 64) {
        #pragma unroll
        for (int it = 0; it < 4; it++) {
            int r = it * 16 + rr;
            float4 pv = *(const float4*)(P + ((size_t)bh*TT + i0 + r) * TT + j0 + c4);
            Ps[c4+0][r] = pv.x; Ps[c4+1][r] = pv.y; Ps[c4+2][r] = pv.z; Ps[c4+3][r] = pv.w;
            float4 vv = *(const float4*)(V + (size_t)(b*TT + j0 + r) * DD + h*DKK + c4);
            *(float4*)&Vs[r][c4] = vv;
        }
        __syncthreads();

        #pragma unroll 8
        for (int j = 0; j < 64; j++) {
            float a[4], bb2[4];
            #pragma unroll
            for (int i = 0; i < 4; i++) a[i]   = Ps[j][ty*4 + i];
            #pragma unroll
            for (int u = 0; u < 4; u++) bb2[u] = Vs[j][tx*4 + u];
            #pragma unroll
            for (int i = 0; i < 4; i++)
                #pragma unroll
                for (int u = 0; u < 4; u++)
                    acc[i][u] = fmaf(a[i], bb2[u], acc[i][u]);
        }
        __syncthreads();
    }

    #pragma unroll
    for (int i = 0; i < 4; i++) {
        float* Op = O + (size_t)(b*TT + i0 + ty*4 + i) * DD + h*DKK + tx*4;
        *(float4*)Op = make_float4(acc[i][0], acc[i][1], acc[i][2], acc[i][3]);
    }
}

// ---------------------------------------------------------------------------
// Fused residual + LayerNorm: out[row,:] = LN(a[row,:] + r[row,:]) * g + beta
// One block (256 threads) per row of D=1024.
// ---------------------------------------------------------------------------
__global__ __launch_bounds__(256) void add_ln_kernel(
    const float* __restrict__ A, const float* __restrict__ R,
    const float* __restrict__ g, const float* __restrict__ beta,
    float* __restrict__ out)
{
    __shared__ float red[256];
    const int tid = threadIdx.x;
    const size_t base = (size_t)blockIdx.x * DD;

    float x[4];
    float s = 0.f;
    #pragma unroll
    for (int u = 0; u < 4; u++) {
        int c = tid + 256*u;
        x[u] = A[base + c] + R[base + c];
        s += x[u];
    }
    red[tid] = s;
    __syncthreads();
    for (int t = 128; t > 0; t >>= 1) {
        if (tid < t) red[tid] += red[tid + t];
        __syncthreads();
    }
    const float mu = red[0] * (1.f / DD);
    __syncthreads();

    float vs = 0.f;
    #pragma unroll
    for (int u = 0; u < 4; u++) {
        float d = x[u] - mu;
        vs += d * d;
    }
    red[tid] = vs;
    __syncthreads();
    for (int t = 128; t > 0; t >>= 1) {
        if (tid < t) red[tid] += red[tid + t];
        __syncthreads();
    }
    const float inv = rsqrtf(red[0] * (1.f / DD) + LNEPS);

    #pragma unroll
    for (int u = 0; u < 4; u++) {
        int c = tid + 256*u;
        out[base + c] = (x[u] - mu) * inv * g[c] + beta[c];
    }
}

// ---------------------------------------------------------------------------
// Launch
// ---------------------------------------------------------------------------
extern "C" void kernel_launch(void* const* d_in, const int* in_sizes, int n_in,
                              void* d_out, int out_size)
{
    const float* x    = (const float*)d_in[0];
    const float* Wq   = (const float*)d_in[1];
    const float* Wk   = (const float*)d_in[2];
    const float* Wv   = (const float*)d_in[3];
    const float* W1   = (const float*)d_in[4];
    const float* b1   = (const float*)d_in[5];
    const float* W2   = (const float*)d_in[6];
    const float* b2   = (const float*)d_in[7];
    const float* ln1g = (const float*)d_in[8];
    const float* ln1b = (const float*)d_in[9];
    const float* ln2g = (const float*)d_in[10];
    const float* ln2b = (const float*)d_in[11];

    float *q, *k, *v, *att, *sc, *x1, *hid, *ff;
    cudaGetSymbolAddress((void**)&q,   g_q);
    cudaGetSymbolAddress((void**)&k,   g_k);
    cudaGetSymbolAddress((void**)&v,   g_v);
    cudaGetSymbolAddress((void**)&att, g_att);
    cudaGetSymbolAddress((void**)&sc,  g_scores);
    cudaGetSymbolAddress((void**)&x1,  g_x1);
    cudaGetSymbolAddress((void**)&hid, g_hid);
    cudaGetSymbolAddress((void**)&ff,  g_ff);

    // QKV projections: (4096,1024) = (4096,1024) @ (1024,1024)
    dim3 gQKV(DD/128, MROWS/128);
    sgemm_kernel<<<gQKV, 256>>>(x, Wq, q, MROWS, DD, DD, nullptr, 0);
    sgemm_kernel<<<gQKV, 256>>>(x, Wk, k, MROWS, DD, DD, nullptr, 0);
    sgemm_kernel<<<gQKV, 256>>>(x, Wv, v, MROWS, DD, DD, nullptr, 0);

    // Scores + softmax + PV
    attn_scores_kernel<<<dim3(TT/64, TT/64, BB*HH), 256>>>(q, k, sc);
    softmax_kernel<<<BB*HH*TT, 256>>>(sc);
    attn_out_kernel<<<dim3(TT/64, 1, BB*HH), 256>>>(sc, v, att);

    // x1 = LN(x + att)
    add_ln_kernel<<<MROWS, 256>>>(x, att, ln1g, ln1b, x1);

    // FFN
    sgemm_kernel<<<dim3(DFF/128, MROWS/128), 256>>>(x1, W1, hid, MROWS, DFF, DD, b1, 1);
    sgemm_kernel<<<dim3(DD/128, MROWS/128), 256>>>(hid, W2, ff, MROWS, DD, DFF, b2, 0);

    // out = LN(x1 + ff)
    add_ln_kernel<<<MROWS, 256>>>(x1, ff, ln2g, ln2b, (float*)d_out);
}

// round 7
// speedup vs baseline: 2.1667x; 2.1667x over previous
#include <cuda_runtime.h>
#include <math.h>
#include <stdint.h>

// Problem constants
#define BB 4
#define TT 1024
#define DD 1024
#define HH 16
#define DKK 64
#define DFF 4096
#define MROWS (BB*TT)            // 4096
#define LNEPS 1e-5f

// ---------------------------------------------------------------------------
// Scratch (static __device__ arrays — no allocation allowed)
// ---------------------------------------------------------------------------
__device__ float g_q[MROWS*DD];
__device__ float g_k[MROWS*DD];
__device__ float g_v[MROWS*DD];
__device__ float g_att[MROWS*DD];
__device__ float g_x1[MROWS*DD];
__device__ float g_hid[(size_t)MROWS*DFF];        // 64 MB
__device__ float g_ff[MROWS*DD];

// ---------------------------------------------------------------------------
// TF32 helpers
// ---------------------------------------------------------------------------
__device__ __forceinline__ float f2tf32(float x) {
    uint32_t u;
    asm("cvt.rna.tf32.f32 %0, %1;" : "=r"(u) : "f"(x));
    return __uint_as_float(u);
}

__device__ __forceinline__ void mma_tf32(
    float& d0, float& d1, float& d2, float& d3,
    uint32_t a0, uint32_t a1, uint32_t a2, uint32_t a3,
    uint32_t b0, uint32_t b1)
{
    asm volatile(
        "mma.sync.aligned.m16n8k8.row.col.f32.tf32.tf32.f32 "
        "{%0,%1,%2,%3}, {%4,%5,%6,%7}, {%8,%9}, {%0,%1,%2,%3};"
        : "+f"(d0), "+f"(d1), "+f"(d2), "+f"(d3)
        : "r"(a0), "r"(a1), "r"(a2), "r"(a3), "r"(b0), "r"(b1));
}

// ---------------------------------------------------------------------------
// TF32 tensor-core GEMM core: C[M,N] = A[M,K] @ B[K,N] (+bias, optional ReLU)
// 128x128 block tile, BK=32, 256 threads (8 warps as 2x4, 64x32 per warp).
// ---------------------------------------------------------------------------
#define AS_STRIDE 36
#define BS_STRIDE 132

__device__ __forceinline__ void mma_gemm_body(
    const float* __restrict__ A, const float* __restrict__ B,
    float* __restrict__ C, int N, int K,
    const float* __restrict__ bias, int relu,
    int brow, int bcol)
{
    __shared__ __align__(16) float As[128 * AS_STRIDE];   // 18 KB
    __shared__ __align__(16) float Bs[32 * BS_STRIDE];    // 16.5 KB

    const int tid  = threadIdx.x;
    const int wid  = tid >> 5;
    const int lane = tid & 31;
    const int g    = lane >> 2;        // groupID (0..7)
    const int tr   = lane & 3;         // thread-in-group (0..3)

    const int warp_m = (wid >> 2) * 64;   // 0 or 64
    const int warp_n = (wid & 3) * 32;    // 0,32,64,96

    int a_row[4], a_c4[4], b_row[4], b_c4[4];
    #pragma unroll
    for (int i = 0; i < 4; i++) {
        int e = tid + 256 * i;
        a_row[i] = e >> 3;  a_c4[i] = (e & 7) * 4;
        b_row[i] = e >> 5;  b_c4[i] = (e & 31) * 4;
    }

    float acc[4][4][4];
    #pragma unroll
    for (int mi = 0; mi < 4; mi++)
        #pragma unroll
        for (int ni = 0; ni < 4; ni++)
            #pragma unroll
            for (int r = 0; r < 4; r++) acc[mi][ni][r] = 0.f;

    float4 pa[4], pb[4];
    #pragma unroll
    for (int i = 0; i < 4; i++) {
        pa[i] = *(const float4*)(A + (size_t)(brow + a_row[i]) * K + a_c4[i]);
        pb[i] = *(const float4*)(B + (size_t)b_row[i] * N + bcol + b_c4[i]);
    }

    for (int kt = 0; kt < K; kt += 32) {
        #pragma unroll
        for (int i = 0; i < 4; i++) {
            float4 va = make_float4(f2tf32(pa[i].x), f2tf32(pa[i].y),
                                    f2tf32(pa[i].z), f2tf32(pa[i].w));
            *(float4*)&As[a_row[i] * AS_STRIDE + a_c4[i]] = va;
            float4 vb = make_float4(f2tf32(pb[i].x), f2tf32(pb[i].y),
                                    f2tf32(pb[i].z), f2tf32(pb[i].w));
            *(float4*)&Bs[b_row[i] * BS_STRIDE + b_c4[i]] = vb;
        }
        __syncthreads();

        if (kt + 32 < K) {
            #pragma unroll
            for (int i = 0; i < 4; i++) {
                pa[i] = *(const float4*)(A + (size_t)(brow + a_row[i]) * K + kt + 32 + a_c4[i]);
                pb[i] = *(const float4*)(B + (size_t)(kt + 32 + b_row[i]) * N + bcol + b_c4[i]);
            }
        }

        #pragma unroll
        for (int k8 = 0; k8 < 4; k8++) {
            const int kofs = k8 * 8;
            uint32_t af[4][4];
            #pragma unroll
            for (int mi = 0; mi < 4; mi++) {
                int r0 = warp_m + mi * 16 + g;
                af[mi][0] = __float_as_uint(As[(r0)     * AS_STRIDE + kofs + tr]);
                af[mi][1] = __float_as_uint(As[(r0 + 8) * AS_STRIDE + kofs + tr]);
                af[mi][2] = __float_as_uint(As[(r0)     * AS_STRIDE + kofs + tr + 4]);
                af[mi][3] = __float_as_uint(As[(r0 + 8) * AS_STRIDE + kofs + tr + 4]);
            }
            uint32_t bf[4][2];
            #pragma unroll
            for (int ni = 0; ni < 4; ni++) {
                int c0 = warp_n + ni * 8 + g;
                bf[ni][0] = __float_as_uint(Bs[(kofs + tr)     * BS_STRIDE + c0]);
                bf[ni][1] = __float_as_uint(Bs[(kofs + tr + 4) * BS_STRIDE + c0]);
            }
            #pragma unroll
            for (int mi = 0; mi < 4; mi++)
                #pragma unroll
                for (int ni = 0; ni < 4; ni++)
                    mma_tf32(acc[mi][ni][0], acc[mi][ni][1],
                             acc[mi][ni][2], acc[mi][ni][3],
                             af[mi][0], af[mi][1], af[mi][2], af[mi][3],
                             bf[ni][0], bf[ni][1]);
        }
        __syncthreads();
    }

    #pragma unroll
    for (int ni = 0; ni < 4; ni++) {
        const int col = bcol + warp_n + ni * 8 + tr * 2;
        float bv0 = bias ? bias[col]     : 0.f;
        float bv1 = bias ? bias[col + 1] : 0.f;
        #pragma unroll
        for (int mi = 0; mi < 4; mi++) {
            const int row = brow + warp_m + mi * 16 + g;
            float v0 = acc[mi][ni][0] + bv0;
            float v1 = acc[mi][ni][1] + bv1;
            float v2 = acc[mi][ni][2] + bv0;
            float v3 = acc[mi][ni][3] + bv1;
            if (relu) {
                v0 = fmaxf(v0, 0.f); v1 = fmaxf(v1, 0.f);
                v2 = fmaxf(v2, 0.f); v3 = fmaxf(v3, 0.f);
            }
            *(float2*)(C + (size_t)row * N + col)       = make_float2(v0, v1);
            *(float2*)(C + (size_t)(row + 8) * N + col) = make_float2(v2, v3);
        }
    }
}

__global__ __launch_bounds__(256) void mma_gemm_kernel(
    const float* __restrict__ A, const float* __restrict__ B,
    float* __restrict__ C, int M, int N, int K,
    const float* __restrict__ bias, int relu)
{
    mma_gemm_body(A, B, C, N, K, bias, relu,
                  blockIdx.y * 128, blockIdx.x * 128);
}

// Batched QKV: z selects (Wq->q | Wk->k | Wv->v); shared A = x.
__global__ __launch_bounds__(256) void mma_qkv_kernel(
    const float* __restrict__ X,
    const float* __restrict__ Wq, const float* __restrict__ Wk,
    const float* __restrict__ Wv,
    float* __restrict__ Q, float* __restrict__ K_, float* __restrict__ V)
{
    const float* B = (blockIdx.z == 0) ? Wq : (blockIdx.z == 1) ? Wk : Wv;
    float*       C = (blockIdx.z == 0) ? Q  : (blockIdx.z == 1) ? K_ : V;
    mma_gemm_body(X, B, C, DD, DD, nullptr, 0,
                  blockIdx.y * 128, blockIdx.x * 128);
}

// ---------------------------------------------------------------------------
// Fused flash attention (fp32 SIMT): per (b,h), 64 q-rows per block.
// Merges the previously-passing attn_scores + softmax + attn_out kernels with
// online softmax; scores never touch global memory.
// grid = (T/64, 1, B*H), 256 threads.
// Thread (ty=tid>>4, tx=tid&15) owns score tile rows ty*4..+3, cols tx*4..+3,
// and output rows ty*4..+3, dims tx*4..+3.
// Row reduction = shuffle over 16-lane segments (same ty <=> same half-warp).
// ---------------------------------------------------------------------------
__global__ __launch_bounds__(256) void flash_attn_kernel(
    const float* __restrict__ Q, const float* __restrict__ K,
    const float* __restrict__ V, float* __restrict__ O)
{
    __shared__ __align__(16) float Qs[64][65];   // [d][i]
    __shared__ __align__(16) float Ks[64][65];   // [d][j]
    __shared__ __align__(16) float Ps[64][65];   // [j][i]
    __shared__ __align__(16) float Vs[64][64];   // [j][d]

    const int tid = threadIdx.x;
    const int bh = blockIdx.z;
    const int b  = bh >> 4;            // / HH
    const int h  = bh & 15;            // % HH
    const int i0 = blockIdx.x * 64;

    const int rr = tid >> 4;           // 0..15
    const int c4 = (tid & 15) * 4;     // 0..60
    const int ty = tid >> 4;
    const int tx = tid & 15;

    // Load Q tile once: Qs[d][i]
    #pragma unroll
    for (int it = 0; it < 4; it++) {
        int r = it * 16 + rr;
        float4 qv = *(const float4*)(Q + (size_t)(b*TT + i0 + r) * DD + h*DKK + c4);
        Qs[c4+0][r] = qv.x; Qs[c4+1][r] = qv.y; Qs[c4+2][r] = qv.z; Qs[c4+3][r] = qv.w;
    }

    float acc[4][4];
    #pragma unroll
    for (int i = 0; i < 4; i++)
        #pragma unroll
        for (int u = 0; u < 4; u++) acc[i][u] = 0.f;
    float mrun[4] = {-1e30f, -1e30f, -1e30f, -1e30f};
    float lrun[4] = {0.f, 0.f, 0.f, 0.f};

    for (int j0 = 0; j0 < TT; j0 += 64) {
        // Load K tile (Ks[d][j]) and V tile (Vs[j][d])
        #pragma unroll
        for (int it = 0; it < 4; it++) {
            int r = it * 16 + rr;
            float4 kv = *(const float4*)(K + (size_t)(b*TT + j0 + r) * DD + h*DKK + c4);
            Ks[c4+0][r] = kv.x; Ks[c4+1][r] = kv.y; Ks[c4+2][r] = kv.z; Ks[c4+3][r] = kv.w;
            float4 vv = *(const float4*)(V + (size_t)(b*TT + j0 + r) * DD + h*DKK + c4);
            *(float4*)&Vs[r][c4] = vv;
        }
        __syncthreads();   // S1: tiles visible; prev-iter Ps/Vs reads done (S3)

        // Scores: s[i][j] = (Q_row . K_row) * 0.125
        float s[4][4];
        #pragma unroll
        for (int i = 0; i < 4; i++)
            #pragma unroll
            for (int j = 0; j < 4; j++) s[i][j] = 0.f;
        #pragma unroll 8
        for (int d = 0; d < 64; d++) {
            float a[4], b2[4];
            #pragma unroll
            for (int i = 0; i < 4; i++) a[i]  = Qs[d][ty*4 + i];
            #pragma unroll
            for (int j = 0; j < 4; j++) b2[j] = Ks[d][tx*4 + j];
            #pragma unroll
            for (int i = 0; i < 4; i++)
                #pragma unroll
                for (int j = 0; j < 4; j++)
                    s[i][j] = fmaf(a[i], b2[j], s[i][j]);
        }

        // Online softmax update per row i
        float scale[4];
        #pragma unroll
        for (int i = 0; i < 4; i++) {
            float rm = fmaxf(fmaxf(s[i][0], s[i][1]), fmaxf(s[i][2], s[i][3])) * 0.125f;
            #pragma unroll
            for (int o = 8; o > 0; o >>= 1)
                rm = fmaxf(rm, __shfl_xor_sync(0xffffffffu, rm, o));
            float mnew = fmaxf(mrun[i], rm);
            scale[i] = __expf(mrun[i] - mnew);
            mrun[i] = mnew;

            float rs = 0.f;
            #pragma unroll
            for (int j = 0; j < 4; j++) {
                float p = __expf(s[i][j] * 0.125f - mnew);
                s[i][j] = p;          // reuse s as p
                rs += p;
            }
            #pragma unroll
            for (int o = 8; o > 0; o >>= 1)
                rs += __shfl_xor_sync(0xffffffffu, rs, o);
            lrun[i] = lrun[i] * scale[i] + rs;

            #pragma unroll
            for (int u = 0; u < 4; u++) acc[i][u] *= scale[i];
        }

        // Publish P tile: Ps[j][i]
        #pragma unroll
        for (int i = 0; i < 4; i++)
            #pragma unroll
            for (int j = 0; j < 4; j++)
                Ps[tx*4 + j][ty*4 + i] = s[i][j];
        __syncthreads();   // S2: Ps visible

        // acc += P · V  (rows ty*4+i, dims tx*4+u)
        #pragma unroll 8
        for (int j = 0; j < 64; j++) {
            float a[4], b2[4];
            #pragma unroll
            for (int i = 0; i < 4; i++) a[i]  = Ps[j][ty*4 + i];
            #pragma unroll
            for (int u = 0; u < 4; u++) b2[u] = Vs[j][tx*4 + u];
            #pragma unroll
            for (int i = 0; i < 4; i++)
                #pragma unroll
                for (int u = 0; u < 4; u++)
                    acc[i][u] = fmaf(a[i], b2[u], acc[i][u]);
        }
        __syncthreads();   // S3: reads done before next iter's stores
    }

    // Final normalize + store
    #pragma unroll
    for (int i = 0; i < 4; i++) {
        float inv = 1.f / lrun[i];
        float* Op = O + (size_t)(b*TT + i0 + ty*4 + i) * DD + h*DKK + tx*4;
        *(float4*)Op = make_float4(acc[i][0]*inv, acc[i][1]*inv,
                                   acc[i][2]*inv, acc[i][3]*inv);
    }
}

// ---------------------------------------------------------------------------
// Block reduction helpers: smem tree to 32 partials, then warp shuffle.
// ---------------------------------------------------------------------------
__device__ __forceinline__ float block_reduce_sum256(float v, float* red, int tid)
{
    red[tid] = v;
    __syncthreads();
    if (tid < 128) red[tid] += red[tid + 128];
    __syncthreads();
    if (tid < 64)  red[tid] += red[tid + 64];
    __syncthreads();
    if (tid < 32) {
        float s = red[tid] + red[tid + 32];
        #pragma unroll
        for (int o = 16; o > 0; o >>= 1)
            s += __shfl_xor_sync(0xffffffffu, s, o);
        red[tid] = s;
    }
    __syncthreads();
    return red[0];
}

// ---------------------------------------------------------------------------
// Fused residual + LayerNorm: out[row,:] = LN(a[row,:] + r[row,:]) * g + beta
// ---------------------------------------------------------------------------
__global__ __launch_bounds__(256) void add_ln_kernel(
    const float* __restrict__ A, const float* __restrict__ R,
    const float* __restrict__ g, const float* __restrict__ beta,
    float* __restrict__ out)
{
    __shared__ float red[256];
    const int tid = threadIdx.x;
    const size_t base = (size_t)blockIdx.x * DD;

    float x[4];
    float s = 0.f;
    #pragma unroll
    for (int u = 0; u < 4; u++) {
        int c = tid + 256*u;
        x[u] = A[base + c] + R[base + c];
        s += x[u];
    }
    s = block_reduce_sum256(s, red, tid);
    const float mu = s * (1.f / DD);

    float vs = 0.f;
    #pragma unroll
    for (int u = 0; u < 4; u++) {
        float d = x[u] - mu;
        vs += d * d;
    }
    vs = block_reduce_sum256(vs, red, tid);
    const float inv = rsqrtf(vs * (1.f / DD) + LNEPS);

    #pragma unroll
    for (int u = 0; u < 4; u++) {
        int c = tid + 256*u;
        out[base + c] = (x[u] - mu) * inv * g[c] + beta[c];
    }
}

// ---------------------------------------------------------------------------
// Launch
// ---------------------------------------------------------------------------
extern "C" void kernel_launch(void* const* d_in, const int* in_sizes, int n_in,
                              void* d_out, int out_size)
{
    const float* x    = (const float*)d_in[0];
    const float* Wq   = (const float*)d_in[1];
    const float* Wk   = (const float*)d_in[2];
    const float* Wv   = (const float*)d_in[3];
    const float* W1   = (const float*)d_in[4];
    const float* b1   = (const float*)d_in[5];
    const float* W2   = (const float*)d_in[6];
    const float* b2   = (const float*)d_in[7];
    const float* ln1g = (const float*)d_in[8];
    const float* ln1b = (const float*)d_in[9];
    const float* ln2g = (const float*)d_in[10];
    const float* ln2b = (const float*)d_in[11];

    float *q, *k, *v, *att, *x1, *hid, *ff;
    cudaGetSymbolAddress((void**)&q,   g_q);
    cudaGetSymbolAddress((void**)&k,   g_k);
    cudaGetSymbolAddress((void**)&v,   g_v);
    cudaGetSymbolAddress((void**)&att, g_att);
    cudaGetSymbolAddress((void**)&x1,  g_x1);
    cudaGetSymbolAddress((void**)&hid, g_hid);
    cudaGetSymbolAddress((void**)&ff,  g_ff);

    // QKV projections, batched over gridDim.z  [tf32 MMA]
    mma_qkv_kernel<<<dim3(DD/128, MROWS/128, 3), 256>>>(x, Wq, Wk, Wv, q, k, v);

    // Fused flash attention (fp32 SIMT), replaces scores+softmax+PV
    flash_attn_kernel<<<dim3(TT/64, 1, BB*HH), 256>>>(q, k, v, att);

    // x1 = LN(x + att)
    add_ln_kernel<<<MROWS, 256>>>(x, att, ln1g, ln1b, x1);

    // FFN  [tf32 MMA]
    mma_gemm_kernel<<<dim3(DFF/128, MROWS/128), 256>>>(x1, W1, hid, MROWS, DFF, DD, b1, 1);
    mma_gemm_kernel<<<dim3(DD/128, MROWS/128), 256>>>(hid, W2, ff, MROWS, DD, DFF, b2, 0);

    // out = LN(x1 + ff)
    add_ln_kernel<<<MROWS, 256>>>(x1, ff, ln2g, ln2b, (float*)d_out);
}